// round 12
// baseline (speedup 1.0000x reference)
#include <cuda_runtime.h>
#include <cuda_fp16.h>
#include <cstdint>

// ---------------------------------------------------------------------------
// ShapletLearner via single-pass fp16 mma.sync m16n8k16.
// R12 = R11 + L1/shared-traffic diet:
//   - wsq via prefix-sum of squares (coalesced scan; no 9-wavefront LDS storm)
//   - ring pairs packed as uint2 (1 LDS.64/tile), wq packed as float2
//     (1 LDS.64/tile) -> 2 LDS per tile total (was 4)
//   - B pre-scaled by -2, wsq folded into HMMA C operand (from R11)
// ---------------------------------------------------------------------------

constexpr int Bc = 2048;
constexpr int Qc = 1024;
constexpr int Kc = 32;
constexpr int Lc = 64;
constexpr int Sc = Qc - Kc + 1;   // 993

// D = A*B + {c0,c0,c1,c1}
#define MMAC(d0,d1,d2,d3, a0,a1,a2,a3, b0,b1, c0,c1) \
    asm("mma.sync.aligned.m16n8k16.row.col.f32.f16.f16.f32 " \
        "{%0,%1,%2,%3}, {%4,%5,%6,%7}, {%8,%9}, {%10,%11,%12,%13};" \
        : "=f"(d0), "=f"(d1), "=f"(d2), "=f"(d3) \
        : "r"(a0), "r"(a1), "r"(a2), "r"(a3), "r"(b0), "r"(b1), \
          "f"(c0), "f"(c0), "f"(c1), "f"(c1))

// D += A*B
#define MMAB(d0,d1,d2,d3, a0,a1,a2,a3, b0,b1) \
    asm("mma.sync.aligned.m16n8k16.row.col.f32.f16.f16.f32 " \
        "{%0,%1,%2,%3}, {%4,%5,%6,%7}, {%8,%9}, {%0,%1,%2,%3};" \
        : "+f"(d0), "+f"(d1), "+f"(d2), "+f"(d3) \
        : "r"(a0), "r"(a1), "r"(a2), "r"(a3), "r"(b0), "r"(b1))

// One m16 tile into accumulator set S. wqS was prefetched 2 tiles ago.
// Refills: wq for tile TT+2 (1 LDS.64), ring pairs for tile TT+1 (1 LDS.64).
#define TILE_MMA(O, S, TT) do { \
    enum { I0 = (O) % 6, I1 = ((O) + 1) % 6, I2 = ((O) + 2) % 6, \
           I3 = ((O) + 3) % 6, I4 = ((O) + 4) % 6, S5 = ((O) + 5) % 6 }; \
    const int s0_ = (TT) << 4; \
    MMAC(d##S##0,d##S##1,d##S##2,d##S##3, rr[I0],rr[I1],rr[I1],rr[I2], \
         Bf[0][0][0],Bf[0][0][1], wq##S.x, wq##S.y); \
    MMAC(d##S##4,d##S##5,d##S##6,d##S##7, rr[I0],rr[I1],rr[I1],rr[I2], \
         Bf[1][0][0],Bf[1][0][1], wq##S.x, wq##S.y); \
    MMAB(d##S##0,d##S##1,d##S##2,d##S##3, rr[I2],rr[I3],rr[I3],rr[I4], \
         Bf[0][1][0],Bf[0][1][1]); \
    MMAB(d##S##4,d##S##5,d##S##6,d##S##7, rr[I2],rr[I3],rr[I3],rr[I4], \
         Bf[1][1][0],Bf[1][1][1]); \
    wq##S = wqp[(TT) * 8 + 16 + nrow]; \
    { const uint2 p_ = pp[s0_ + tb + 40]; \
      rr[S5] = p_.x;  rr[I0] = p_.y; } \
} while (0)

// merge set S (raw dist) into running mins — 8 FMNMX
#define MERGE_S(S) do { \
    mn00 = fminf(mn00, d##S##0);  mn01 = fminf(mn01, d##S##1); \
    mn02 = fminf(mn02, d##S##2);  mn03 = fminf(mn03, d##S##3); \
    mn10 = fminf(mn10, d##S##4);  mn11 = fminf(mn11, d##S##5); \
    mn12 = fminf(mn12, d##S##6);  mn13 = fminf(mn13, d##S##7); \
} while (0)

static __device__ __forceinline__ uint32_t pack_f16x2(float lo, float hi) {
    uint32_t r;
    asm("cvt.rn.f16x2.f32 %0, %1, %2;" : "=r"(r) : "f"(hi), "f"(lo));
    return r;
}

__global__ __launch_bounds__(128) void shapelet_hmma(
    const float* __restrict__ ts,        // [B, Q]
    const float* __restrict__ shp,       // [L, K]
    const float* __restrict__ fc_w,      // [2, L]
    const float* __restrict__ fc_b,      // [2]
    float* __restrict__ out)             // [B, 2]
{
    __shared__ __align__(16) float  ts_sh[1152];   // fp32, zero-padded
    __shared__ __align__(16) float  P[1056];       // prefix of squares [0..1024]
    __shared__ __align__(16) uint2  pp[1120];      // {pair16[i], pair16[i+8]}
    __shared__ __align__(16) float2 wqp[544];      // {wsq[16t+r], wsq[16t+r+8]}
    __shared__ float warp_tot[4];
    __shared__ float ssq_sh[Lc];
    __shared__ float dsh[Lc];

    const int b    = blockIdx.x;
    const int tid  = threadIdx.x;
    const int w    = tid >> 5;
    const int lane = tid & 31;
    const int nrow = lane >> 2;
    const int kq   = lane & 3;

    // ---- stage ts + zero pad to 1152 ----
    {
        const float4* src = reinterpret_cast<const float4*>(ts + (size_t)b * Qc);
        float4* dst = reinterpret_cast<float4*>(ts_sh);
        dst[tid]       = src[tid];
        dst[128 + tid] = src[128 + tid];
        if (tid < 32) dst[256 + tid] = make_float4(0.f, 0.f, 0.f, 0.f);
    }
    __syncthreads();

    // ---- prefix-sum of squares: P[i] = sum_{j<i} ts[j]^2, i in [0,1024] ----
    {
        const float4 q0 = reinterpret_cast<const float4*>(ts_sh)[tid * 2];
        const float4 q1 = reinterpret_cast<const float4*>(ts_sh)[tid * 2 + 1];
        float sq[8] = { q0.x*q0.x, q0.y*q0.y, q0.z*q0.z, q0.w*q0.w,
                        q1.x*q1.x, q1.y*q1.y, q1.z*q1.z, q1.w*q1.w };
        float ex[8];
        float e = 0.f;
        #pragma unroll
        for (int k = 0; k < 8; k++) { ex[k] = e; e += sq[k]; }
        // warp inclusive scan of thread totals
        float v = e;
        #pragma unroll
        for (int off = 1; off < 32; off <<= 1) {
            const float n = __shfl_up_sync(0xffffffffu, v, off);
            if (lane >= off) v += n;
        }
        if (lane == 31) warp_tot[w] = v;
        const float warp_excl = v - e;
        __syncthreads();
        float wb = 0.f;
        #pragma unroll
        for (int j = 0; j < 4; j++) wb += (j < w) ? warp_tot[j] : 0.f;
        const float tb0 = wb + warp_excl;
        #pragma unroll
        for (int k = 0; k < 8; k++) P[tid * 8 + k] = tb0 + ex[k];
        if (tid == 127) P[1024] = tb0 + e;
    }

    // ---- packed fp16 ring pairs pp[i] = {pair(i), pair(i+8)} ----
    #pragma unroll
    for (int i = tid; i < 1120; i += 128)
        pp[i] = make_uint2(pack_f16x2(ts_sh[i],     ts_sh[i + 1]),
                           pack_f16x2(ts_sh[i + 8], ts_sh[i + 9]));

    // ---- ssq[l] exact fp32 (global reads) ----
    if (tid < Lc) {
        float s = 0.f;
        #pragma unroll
        for (int k = 0; k < Kc; k++) {
            const float v = shp[tid * Kc + k];
            s = fmaf(v, v, s);
        }
        ssq_sh[tid] = s;
    }

    // ---- B fragments (fp16, pre-scaled by -2): n = w*16 .. w*16+15 ----
    uint32_t Bf[2][2][2];
    #pragma unroll
    for (int nt = 0; nt < 2; nt++)
        #pragma unroll
        for (int kc = 0; kc < 2; kc++)
            #pragma unroll
            for (int j = 0; j < 2; j++) {
                const int n = w * 16 + nt * 8 + nrow;
                const int k = 16 * kc + 8 * j + 2 * kq;
                Bf[nt][kc][j] = pack_f16x2(-2.0f * shp[n * Kc + k],
                                           -2.0f * shp[n * Kc + k + 1]);
            }
    __syncthreads();   // P ready

    // ---- wqp[t*8+r] = {wsq(16t+r), wsq(16t+r+8)} (coalesced) ----
    #pragma unroll
    for (int i = tid; i < 544; i += 128) {
        const int t = i >> 3, r = i & 7;
        const int s = t * 16 + r;
        const float a = (s     < Sc) ? P[s + 32] - P[s]     : 1e38f;
        const float c = (s + 8 < Sc) ? P[s + 40] - P[s + 8] : 1e38f;
        wqp[i] = make_float2(a, c);
    }
    __syncthreads();

    // ---- main loop: 66 m16 tiles, 6-slot pair ring, pipelined merge ----
    float mn00 = 3.4e38f, mn01 = 3.4e38f, mn02 = 3.4e38f, mn03 = 3.4e38f;
    float mn10 = 3.4e38f, mn11 = 3.4e38f, mn12 = 3.4e38f, mn13 = 3.4e38f;

    const int tb = nrow + 2 * kq;   // in [0,13]
    uint32_t rr[6];
    {
        const uint2 u0 = pp[tb];
        const uint2 u1 = pp[tb + 16];
        const uint2 u2 = pp[tb + 32];
        rr[0] = u0.x; rr[1] = u0.y;
        rr[2] = u1.x; rr[3] = u1.y;
        rr[4] = u2.x; rr[5] = 0u;
    }

    float dA0,dA1,dA2,dA3,dA4,dA5,dA6,dA7;
    float dB0,dB1,dB2,dB3,dB4,dB5,dB6,dB7;

    // wq prologue: set A serves tile 0, set B serves tile 1
    float2 wqA = wqp[nrow];
    float2 wqB = wqp[8 + nrow];

    #pragma unroll 1
    for (int it = 0; it < 11; it++) {
        const int t6 = it * 6;
        TILE_MMA(0, A, t6);
        TILE_MMA(2, B, t6 + 1);
        MERGE_S(A);
        TILE_MMA(4, A, t6 + 2);
        MERGE_S(B);
        TILE_MMA(0, B, t6 + 3);
        MERGE_S(A);
        TILE_MMA(2, A, t6 + 4);
        MERGE_S(B);
        TILE_MMA(4, B, t6 + 5);
        MERGE_S(A);
        MERGE_S(B);
    }

    // ---- reduce rows in-thread, then across row groups via shfl ----
    float m0 = fminf(mn00, mn02);
    float m1 = fminf(mn01, mn03);
    float m2 = fminf(mn10, mn12);
    float m3 = fminf(mn11, mn13);
    #pragma unroll
    for (int off = 4; off < 32; off <<= 1) {
        m0 = fminf(m0, __shfl_xor_sync(0xffffffffu, m0, off));
        m1 = fminf(m1, __shfl_xor_sync(0xffffffffu, m1, off));
        m2 = fminf(m2, __shfl_xor_sync(0xffffffffu, m2, off));
        m3 = fminf(m3, __shfl_xor_sync(0xffffffffu, m3, off));
    }
    if (nrow == 0) {
        const int n0 = w * 16 + 2 * kq;
        dsh[n0]     = (m0 + ssq_sh[n0])     * (1.0f / Kc);
        dsh[n0 + 1] = (m1 + ssq_sh[n0 + 1]) * (1.0f / Kc);
        dsh[n0 + 8] = (m2 + ssq_sh[n0 + 8]) * (1.0f / Kc);
        dsh[n0 + 9] = (m3 + ssq_sh[n0 + 9]) * (1.0f / Kc);
    }
    __syncthreads();

    // ---- FC epilogue ----
    if (tid < 2 * 32) {
        const int c = tid >> 5;
        const int l = tid & 31;
        float p = dsh[l] * fc_w[c * Lc + l]
                + dsh[l + 32] * fc_w[c * Lc + l + 32];
        #pragma unroll
        for (int off = 16; off > 0; off >>= 1)
            p += __shfl_down_sync(0xffffffffu, p, off);
        if (l == 0) out[b * 2 + c] = p + fc_b[c];
    }
}

extern "C" void kernel_launch(void* const* d_in, const int* in_sizes, int n_in,
                              void* d_out, int out_size)
{
    (void)in_sizes; (void)n_in; (void)out_size;
    const float* ts   = (const float*)d_in[0];
    const float* shp  = (const float*)d_in[1];
    const float* fc_w = (const float*)d_in[2];
    const float* fc_b = (const float*)d_in[3];
    float* out        = (float*)d_out;
    shapelet_hmma<<<Bc, 128>>>(ts, shp, fc_w, fc_b, out);
}

// round 13
// speedup vs baseline: 1.0258x; 1.0258x over previous
#include <cuda_runtime.h>
#include <cuda_fp16.h>
#include <cstdint>

// ---------------------------------------------------------------------------
// ShapletLearner via single-pass fp16 mma.sync m16n8k16.
// R13 = R11 + fully independent HMMAs per tile: k-chunk0 -> e (C = wsq),
// k-chunk1 -> f (C = 0); dist = e + f merged one tile later (FADD+FMNMX).
// No HMMA->HMMA RAW anywhere; merge deferral covers result latency.
// B pre-scaled by -2; wsq folded into chunk0's C operand.
// ---------------------------------------------------------------------------

constexpr int Bc = 2048;
constexpr int Qc = 1024;
constexpr int Kc = 32;
constexpr int Lc = 64;
constexpr int Sc = Qc - Kc + 1;   // 993

// D = A*B + {c0,c0,c1,c1}
#define MMAC(d0,d1,d2,d3, a0,a1,a2,a3, b0,b1, c0,c1) \
    asm("mma.sync.aligned.m16n8k16.row.col.f32.f16.f16.f32 " \
        "{%0,%1,%2,%3}, {%4,%5,%6,%7}, {%8,%9}, {%10,%11,%12,%13};" \
        : "=f"(d0), "=f"(d1), "=f"(d2), "=f"(d3) \
        : "r"(a0), "r"(a1), "r"(a2), "r"(a3), "r"(b0), "r"(b1), \
          "f"(c0), "f"(c0), "f"(c1), "f"(c1))

// D = A*B (C = 0)
#define MMAZ(d0,d1,d2,d3, a0,a1,a2,a3, b0,b1) \
    asm("mma.sync.aligned.m16n8k16.row.col.f32.f16.f16.f32 " \
        "{%0,%1,%2,%3}, {%4,%5,%6,%7}, {%8,%9}, {%10,%11,%12,%13};" \
        : "=f"(d0), "=f"(d1), "=f"(d2), "=f"(d3) \
        : "r"(a0), "r"(a1), "r"(a2), "r"(a3), "r"(b0), "r"(b1), \
          "f"(0.f), "f"(0.f), "f"(0.f), "f"(0.f))

// One m16 tile into set S: 4 INDEPENDENT HMMAs (e = chunk0 + wq, f = chunk1).
// Then prefetch wq for tile TT+2 and ring pairs for tile TT+1.
#define TILE_MMA(O, S, TT) do { \
    enum { I0 = (O) % 6, I1 = ((O) + 1) % 6, I2 = ((O) + 2) % 6, \
           I3 = ((O) + 3) % 6, I4 = ((O) + 4) % 6, S5 = ((O) + 5) % 6 }; \
    const int s0_ = (TT) << 4; \
    MMAC(e##S##0,e##S##1,e##S##2,e##S##3, rr[I0],rr[I1],rr[I1],rr[I2], \
         Bf[0][0][0],Bf[0][0][1], wq0##S, wq1##S); \
    MMAC(e##S##4,e##S##5,e##S##6,e##S##7, rr[I0],rr[I1],rr[I1],rr[I2], \
         Bf[1][0][0],Bf[1][0][1], wq0##S, wq1##S); \
    MMAZ(f##S##0,f##S##1,f##S##2,f##S##3, rr[I2],rr[I3],rr[I3],rr[I4], \
         Bf[0][1][0],Bf[0][1][1]); \
    MMAZ(f##S##4,f##S##5,f##S##6,f##S##7, rr[I2],rr[I3],rr[I3],rr[I4], \
         Bf[1][1][0],Bf[1][1][1]); \
    wq0##S = wsq_sh[s0_ + 32 + nrow]; \
    wq1##S = wsq_sh[s0_ + 32 + nrow + 8]; \
    { const int gi_ = s0_ + tb; \
      rr[S5] = pair16[gi_ + 40]; \
      rr[I0] = pair16[gi_ + 48]; } \
} while (0)

// merge set S: dist = e + f, then min (deferred one tile)
#define MERGE_S(S) do { \
    mn00 = fminf(mn00, e##S##0 + f##S##0); \
    mn01 = fminf(mn01, e##S##1 + f##S##1); \
    mn02 = fminf(mn02, e##S##2 + f##S##2); \
    mn03 = fminf(mn03, e##S##3 + f##S##3); \
    mn10 = fminf(mn10, e##S##4 + f##S##4); \
    mn11 = fminf(mn11, e##S##5 + f##S##5); \
    mn12 = fminf(mn12, e##S##6 + f##S##6); \
    mn13 = fminf(mn13, e##S##7 + f##S##7); \
} while (0)

static __device__ __forceinline__ uint32_t pack_f16x2(float lo, float hi) {
    uint32_t r;
    asm("cvt.rn.f16x2.f32 %0, %1, %2;" : "=r"(r) : "f"(hi), "f"(lo));
    return r;
}

__global__ __launch_bounds__(128) void shapelet_hmma(
    const float* __restrict__ ts,        // [B, Q]
    const float* __restrict__ shp,       // [L, K]
    const float* __restrict__ fc_w,      // [2, L]
    const float* __restrict__ fc_b,      // [2]
    float* __restrict__ out)             // [B, 2]
{
    __shared__ __align__(16) float    ts_sh[1152];   // fp32, zero-padded
    __shared__ __align__(16) uint32_t pair16[1120];  // (f16 ts[i], f16 ts[i+1])
    __shared__ __align__(16) float wsq_sh[1088];     // 1e38 guard for s >= Sc
    __shared__ float ssq_sh[Lc];
    __shared__ float dsh[Lc];

    const int b    = blockIdx.x;
    const int tid  = threadIdx.x;
    const int w    = tid >> 5;
    const int lane = tid & 31;
    const int nrow = lane >> 2;
    const int kq   = lane & 3;

    // ---- stage ts + zero pad to 1152 ----
    {
        const float4* src = reinterpret_cast<const float4*>(ts + (size_t)b * Qc);
        float4* dst = reinterpret_cast<float4*>(ts_sh);
        dst[tid]       = src[tid];
        dst[128 + tid] = src[128 + tid];
        if (tid < 32) dst[256 + tid] = make_float4(0.f, 0.f, 0.f, 0.f);
    }
    __syncthreads();

    // ---- packed fp16 pair array ----
    #pragma unroll
    for (int i = tid; i < 1120; i += 128)
        pair16[i] = pack_f16x2(ts_sh[i], ts_sh[i + 1]);

    // ---- wsq[s] exact fp32 (incremental, 9 windows / thread) ----
    {
        const int sbase = tid * 9;
        if (sbase < 1088) {
            float ww = 0.f;
            #pragma unroll
            for (int k = 0; k < Kc; k++) {
                const float x = ts_sh[sbase + k];
                ww = fmaf(x, x, ww);
            }
            wsq_sh[sbase] = (sbase < Sc) ? ww : 1e38f;
            #pragma unroll
            for (int i = 1; i < 9; i++) {
                const int s = sbase + i;
                const float xo = ts_sh[s - 1], xn = ts_sh[s + 31];
                ww = ww - xo * xo + xn * xn;
                if (s < 1088) wsq_sh[s] = (s < Sc) ? ww : 1e38f;
            }
        }
    }

    // ---- ssq[l] exact fp32 ----
    if (tid < Lc) {
        float s = 0.f;
        #pragma unroll
        for (int k = 0; k < Kc; k++) {
            const float v = shp[tid * Kc + k];
            s = fmaf(v, v, s);
        }
        ssq_sh[tid] = s;
    }

    // ---- B fragments (fp16, pre-scaled by -2): n = w*16 .. w*16+15 ----
    uint32_t Bf[2][2][2];
    #pragma unroll
    for (int nt = 0; nt < 2; nt++)
        #pragma unroll
        for (int kc = 0; kc < 2; kc++)
            #pragma unroll
            for (int j = 0; j < 2; j++) {
                const int n = w * 16 + nt * 8 + nrow;
                const int k = 16 * kc + 8 * j + 2 * kq;
                Bf[nt][kc][j] = pack_f16x2(-2.0f * shp[n * Kc + k],
                                           -2.0f * shp[n * Kc + k + 1]);
            }
    __syncthreads();

    // ---- main loop: 66 m16 tiles, 6-slot pair ring, pipelined merge ----
    float mn00 = 3.4e38f, mn01 = 3.4e38f, mn02 = 3.4e38f, mn03 = 3.4e38f;
    float mn10 = 3.4e38f, mn11 = 3.4e38f, mn12 = 3.4e38f, mn13 = 3.4e38f;

    const int tb = nrow + 2 * kq;   // in [0,13]
    uint32_t rr[6];
    #pragma unroll
    for (int m = 0; m < 5; m++) rr[m] = pair16[tb + 8 * m];
    rr[5] = 0u;

    float eA0,eA1,eA2,eA3,eA4,eA5,eA6,eA7;
    float fA0,fA1,fA2,fA3,fA4,fA5,fA6,fA7;
    float eB0,eB1,eB2,eB3,eB4,eB5,eB6,eB7;
    float fB0,fB1,fB2,fB3,fB4,fB5,fB6,fB7;

    // wq prologue: set A serves tile 0, set B serves tile 1
    float wq0A = wsq_sh[nrow],      wq1A = wsq_sh[nrow + 8];
    float wq0B = wsq_sh[16 + nrow], wq1B = wsq_sh[16 + nrow + 8];

    #pragma unroll 1
    for (int it = 0; it < 11; it++) {
        const int t6 = it * 6;
        TILE_MMA(0, A, t6);
        TILE_MMA(2, B, t6 + 1);
        MERGE_S(A);
        TILE_MMA(4, A, t6 + 2);
        MERGE_S(B);
        TILE_MMA(0, B, t6 + 3);
        MERGE_S(A);
        TILE_MMA(2, A, t6 + 4);
        MERGE_S(B);
        TILE_MMA(4, B, t6 + 5);
        MERGE_S(A);
        MERGE_S(B);
    }

    // ---- reduce rows in-thread, then across row groups via shfl ----
    float m0 = fminf(mn00, mn02);
    float m1 = fminf(mn01, mn03);
    float m2 = fminf(mn10, mn12);
    float m3 = fminf(mn11, mn13);
    #pragma unroll
    for (int off = 4; off < 32; off <<= 1) {
        m0 = fminf(m0, __shfl_xor_sync(0xffffffffu, m0, off));
        m1 = fminf(m1, __shfl_xor_sync(0xffffffffu, m1, off));
        m2 = fminf(m2, __shfl_xor_sync(0xffffffffu, m2, off));
        m3 = fminf(m3, __shfl_xor_sync(0xffffffffu, m3, off));
    }
    if (nrow == 0) {
        const int n0 = w * 16 + 2 * kq;
        dsh[n0]     = (m0 + ssq_sh[n0])     * (1.0f / Kc);
        dsh[n0 + 1] = (m1 + ssq_sh[n0 + 1]) * (1.0f / Kc);
        dsh[n0 + 8] = (m2 + ssq_sh[n0 + 8]) * (1.0f / Kc);
        dsh[n0 + 9] = (m3 + ssq_sh[n0 + 9]) * (1.0f / Kc);
    }
    __syncthreads();

    // ---- FC epilogue ----
    if (tid < 2 * 32) {
        const int c = tid >> 5;
        const int l = tid & 31;
        float p = dsh[l] * fc_w[c * Lc + l]
                + dsh[l + 32] * fc_w[c * Lc + l + 32];
        #pragma unroll
        for (int off = 16; off > 0; off >>= 1)
            p += __shfl_down_sync(0xffffffffu, p, off);
        if (l == 0) out[b * 2 + c] = p + fc_b[c];
    }
}

extern "C" void kernel_launch(void* const* d_in, const int* in_sizes, int n_in,
                              void* d_out, int out_size)
{
    (void)in_sizes; (void)n_in; (void)out_size;
    const float* ts   = (const float*)d_in[0];
    const float* shp  = (const float*)d_in[1];
    const float* fc_w = (const float*)d_in[2];
    const float* fc_b = (const float*)d_in[3];
    float* out        = (float*)d_out;
    shapelet_hmma<<<Bc, 128>>>(ts, shp, fc_w, fc_b, out);
}

// round 14
// speedup vs baseline: 1.4416x; 1.4054x over previous
#include <cuda_runtime.h>
#include <cuda_fp16.h>
#include <cstdint>

// ---------------------------------------------------------------------------
// ShapletLearner via single-pass fp16 mma.sync m16n8k16.
// R14 = R11 main loop + L1tex diet in the prologue:
//   - shp staged once (coalesced) into padded SMEM; ssq/B-frags read SMEM
//   - wsq via register scan + shfl (P(s+32)-P(s)); stored transposed so the
//     main loop reads one conflict-free LDS.64 per tile
//   - B pre-scaled by -2; wsq folded into HMMA C operand (R11)
// ---------------------------------------------------------------------------

constexpr int Bc = 2048;
constexpr int Qc = 1024;
constexpr int Kc = 32;
constexpr int Lc = 64;
constexpr int Sc = Qc - Kc + 1;   // 993
constexpr int RS = 164;           // wsq_T row stride (== 4 mod 32: 8 banks)

// D = A*B + {c0,c0,c1,c1}
#define MMAC(d0,d1,d2,d3, a0,a1,a2,a3, b0,b1, c0,c1) \
    asm("mma.sync.aligned.m16n8k16.row.col.f32.f16.f16.f32 " \
        "{%0,%1,%2,%3}, {%4,%5,%6,%7}, {%8,%9}, {%10,%11,%12,%13};" \
        : "=f"(d0), "=f"(d1), "=f"(d2), "=f"(d3) \
        : "r"(a0), "r"(a1), "r"(a2), "r"(a3), "r"(b0), "r"(b1), \
          "f"(c0), "f"(c0), "f"(c1), "f"(c1))

// D += A*B
#define MMAB(d0,d1,d2,d3, a0,a1,a2,a3, b0,b1) \
    asm("mma.sync.aligned.m16n8k16.row.col.f32.f16.f16.f32 " \
        "{%0,%1,%2,%3}, {%4,%5,%6,%7}, {%8,%9}, {%0,%1,%2,%3};" \
        : "+f"(d0), "+f"(d1), "+f"(d2), "+f"(d3) \
        : "r"(a0), "r"(a1), "r"(a2), "r"(a3), "r"(b0), "r"(b1))

// One m16 tile into set S (R11 structure). wqS prefetched 2 tiles ahead via
// one LDS.64 from transposed wsq_T; ring pair refill for tile TT+1.
#define TILE_MMA(O, S, TT) do { \
    enum { I0 = (O) % 6, I1 = ((O) + 1) % 6, I2 = ((O) + 2) % 6, \
           I3 = ((O) + 3) % 6, I4 = ((O) + 4) % 6, S5 = ((O) + 5) % 6 }; \
    const int s0_ = (TT) << 4; \
    MMAC(d##S##0,d##S##1,d##S##2,d##S##3, rr[I0],rr[I1],rr[I1],rr[I2], \
         Bf[0][0][0],Bf[0][0][1], wq##S.x, wq##S.y); \
    MMAC(d##S##4,d##S##5,d##S##6,d##S##7, rr[I0],rr[I1],rr[I1],rr[I2], \
         Bf[1][0][0],Bf[1][0][1], wq##S.x, wq##S.y); \
    MMAB(d##S##0,d##S##1,d##S##2,d##S##3, rr[I2],rr[I3],rr[I3],rr[I4], \
         Bf[0][1][0],Bf[0][1][1]); \
    MMAB(d##S##4,d##S##5,d##S##6,d##S##7, rr[I2],rr[I3],rr[I3],rr[I4], \
         Bf[1][1][0],Bf[1][1][1]); \
    wq##S = *reinterpret_cast<const float2*>(wsq_T + nrowRS + 2 * (TT) + 4); \
    { const int gi_ = s0_ + tb; \
      rr[S5] = pair16[gi_ + 40]; \
      rr[I0] = pair16[gi_ + 48]; } \
} while (0)

// merge set S (raw dist) into running mins — 8 FMNMX (deferred one tile)
#define MERGE_S(S) do { \
    mn00 = fminf(mn00, d##S##0);  mn01 = fminf(mn01, d##S##1); \
    mn02 = fminf(mn02, d##S##2);  mn03 = fminf(mn03, d##S##3); \
    mn10 = fminf(mn10, d##S##4);  mn11 = fminf(mn11, d##S##5); \
    mn12 = fminf(mn12, d##S##6);  mn13 = fminf(mn13, d##S##7); \
} while (0)

static __device__ __forceinline__ uint32_t pack_f16x2(float lo, float hi) {
    uint32_t r;
    asm("cvt.rn.f16x2.f32 %0, %1, %2;" : "=r"(r) : "f"(hi), "f"(lo));
    return r;
}

__global__ __launch_bounds__(128) void shapelet_hmma(
    const float* __restrict__ ts,        // [B, Q]
    const float* __restrict__ shp,       // [L, K]
    const float* __restrict__ fc_w,      // [2, L]
    const float* __restrict__ fc_b,      // [2]
    float* __restrict__ out)             // [B, 2]
{
    __shared__ __align__(16) float    ts_sh[1152];    // fp32, zero-padded
    __shared__ __align__(16) uint32_t pair16[1120];   // (f16 ts[i], ts[i+1])
    __shared__ __align__(16) float    wsq_T[8 * RS];  // transposed wsq
    __shared__ __align__(16) float    shp_sh[Lc * 33];// padded shapelets
    __shared__ float nh[4 * 32];                      // next-warp P heads
    __shared__ float warp_tot[4];
    __shared__ float ssq_sh[Lc];
    __shared__ float dsh[Lc];

    const int b    = blockIdx.x;
    const int tid  = threadIdx.x;
    const int w    = tid >> 5;
    const int lane = tid & 31;
    const int nrow = lane >> 2;
    const int kq   = lane & 3;

    // ---- stage ts (coalesced) + zero pad; stage shp (coalesced, padded) ----
    {
        const float4* src = reinterpret_cast<const float4*>(ts + (size_t)b * Qc);
        float4* dst = reinterpret_cast<float4*>(ts_sh);
        dst[tid]       = src[tid];
        dst[128 + tid] = src[128 + tid];
        if (tid < 32) dst[256 + tid] = make_float4(0.f, 0.f, 0.f, 0.f);
    }
    {
        const float4* gs4 = reinterpret_cast<const float4*>(shp);
        #pragma unroll
        for (int j = 0; j < 4; j++) {
            const int i4 = tid + 128 * j;           // 0..511
            const float4 v = gs4[i4];
            const int base = i4 * 4;
            float* d = &shp_sh[(base >> 5) * 33 + (base & 31)];
            d[0] = v.x; d[1] = v.y; d[2] = v.z; d[3] = v.w;
        }
    }
    __syncthreads();

    // ---- packed fp16 pair array ----
    #pragma unroll
    for (int i = tid; i < 1120; i += 128)
        pair16[i] = pack_f16x2(ts_sh[i], ts_sh[i + 1]);

    // ---- register scan for P(s) = prefix sum of ts^2 ----
    float ex[8], e = 0.f, warp_excl;
    {
        const float4 q0 = reinterpret_cast<const float4*>(ts_sh)[tid * 2];
        const float4 q1 = reinterpret_cast<const float4*>(ts_sh)[tid * 2 + 1];
        const float sq[8] = { q0.x*q0.x, q0.y*q0.y, q0.z*q0.z, q0.w*q0.w,
                              q1.x*q1.x, q1.y*q1.y, q1.z*q1.z, q1.w*q1.w };
        #pragma unroll
        for (int k = 0; k < 8; k++) { ex[k] = e; e += sq[k]; }
        float v = e;
        #pragma unroll
        for (int off = 1; off < 32; off <<= 1) {
            const float n = __shfl_up_sync(0xffffffffu, v, off);
            if (lane >= off) v += n;
        }
        if (lane == 31) warp_tot[w] = v;
        warp_excl = v - e;
    }
    __syncthreads();   // warp_tot ready

    float pk[8], total = 0.f;
    {
        float wb = 0.f;
        #pragma unroll
        for (int j = 0; j < 4; j++) {
            total += warp_tot[j];
            if (j < w) wb += warp_tot[j];
        }
        const float tb0 = wb + warp_excl;
        #pragma unroll
        for (int k = 0; k < 8; k++) pk[k] = tb0 + ex[k];   // P(8*tid+k)
        if (lane < 4) {
            #pragma unroll
            for (int k = 0; k < 8; k++) nh[w * 32 + lane * 8 + k] = pk[k];
        }
    }

    // ---- ssq[l] exact fp32 (from SMEM, conflict-free stride 33) ----
    if (tid < Lc) {
        float s = 0.f;
        #pragma unroll
        for (int k = 0; k < Kc; k++) {
            const float v = shp_sh[tid * 33 + k];
            s = fmaf(v, v, s);
        }
        ssq_sh[tid] = s;
    }

    // ---- B fragments (fp16, pre-scaled by -2) from SMEM ----
    uint32_t Bf[2][2][2];
    #pragma unroll
    for (int nt = 0; nt < 2; nt++)
        #pragma unroll
        for (int kc = 0; kc < 2; kc++)
            #pragma unroll
            for (int j = 0; j < 2; j++) {
                const int n = w * 16 + nt * 8 + nrow;
                const int k = 16 * kc + 8 * j + 2 * kq;
                Bf[nt][kc][j] = pack_f16x2(-2.0f * shp_sh[n * 33 + k],
                                           -2.0f * shp_sh[n * 33 + k + 1]);
            }
    __syncthreads();   // nh ready

    // ---- wsq[s] = P(s+32) - P(s), stored transposed (coalesced STS) ----
    {
        float p4[8];
        #pragma unroll
        for (int k = 0; k < 8; k++)
            p4[k] = __shfl_down_sync(0xffffffffu, pk[k], 4);
        if (lane >= 28 && w < 3) {
            #pragma unroll
            for (int k = 0; k < 8; k++)
                p4[k] = nh[(w + 1) * 32 + (lane - 28) * 8 + k];
        }
        #pragma unroll
        for (int k = 0; k < 8; k++) {
            const int s = tid * 8 + k;
            float wv = 1e38f;
            if (s < Sc) wv = (s == 992) ? (total - pk[k]) : (p4[k] - pk[k]);
            wsq_T[k * RS + tid] = wv;
        }
        if (tid < 64) {   // cover s in [1024, 1088): guard values
            const int s = 1024 + tid;
            wsq_T[(s & 7) * RS + (s >> 3)] = 1e38f;
        }
    }
    __syncthreads();

    // ---- main loop: 66 m16 tiles, 6-slot pair ring, pipelined merge ----
    float mn00 = 3.4e38f, mn01 = 3.4e38f, mn02 = 3.4e38f, mn03 = 3.4e38f;
    float mn10 = 3.4e38f, mn11 = 3.4e38f, mn12 = 3.4e38f, mn13 = 3.4e38f;

    const int tb = nrow + 2 * kq;   // in [0,13]
    const int nrowRS = nrow * RS;
    uint32_t rr[6];
    #pragma unroll
    for (int m = 0; m < 5; m++) rr[m] = pair16[tb + 8 * m];
    rr[5] = 0u;

    float dA0,dA1,dA2,dA3,dA4,dA5,dA6,dA7;
    float dB0,dB1,dB2,dB3,dB4,dB5,dB6,dB7;

    // wq prologue: set A serves tile 0, set B serves tile 1
    float2 wqA = *reinterpret_cast<const float2*>(wsq_T + nrowRS);
    float2 wqB = *reinterpret_cast<const float2*>(wsq_T + nrowRS + 2);

    #pragma unroll 1
    for (int it = 0; it < 11; it++) {
        const int t6 = it * 6;
        TILE_MMA(0, A, t6);
        TILE_MMA(2, B, t6 + 1);
        MERGE_S(A);
        TILE_MMA(4, A, t6 + 2);
        MERGE_S(B);
        TILE_MMA(0, B, t6 + 3);
        MERGE_S(A);
        TILE_MMA(2, A, t6 + 4);
        MERGE_S(B);
        TILE_MMA(4, B, t6 + 5);
        MERGE_S(A);
        MERGE_S(B);
    }

    // ---- reduce rows in-thread, then across row groups via shfl ----
    float m0 = fminf(mn00, mn02);
    float m1 = fminf(mn01, mn03);
    float m2 = fminf(mn10, mn12);
    float m3 = fminf(mn11, mn13);
    #pragma unroll
    for (int off = 4; off < 32; off <<= 1) {
        m0 = fminf(m0, __shfl_xor_sync(0xffffffffu, m0, off));
        m1 = fminf(m1, __shfl_xor_sync(0xffffffffu, m1, off));
        m2 = fminf(m2, __shfl_xor_sync(0xffffffffu, m2, off));
        m3 = fminf(m3, __shfl_xor_sync(0xffffffffu, m3, off));
    }
    if (nrow == 0) {
        const int n0 = w * 16 + 2 * kq;
        dsh[n0]     = (m0 + ssq_sh[n0])     * (1.0f / Kc);
        dsh[n0 + 1] = (m1 + ssq_sh[n0 + 1]) * (1.0f / Kc);
        dsh[n0 + 8] = (m2 + ssq_sh[n0 + 8]) * (1.0f / Kc);
        dsh[n0 + 9] = (m3 + ssq_sh[n0 + 9]) * (1.0f / Kc);
    }
    __syncthreads();

    // ---- FC epilogue ----
    if (tid < 2 * 32) {
        const int c = tid >> 5;
        const int l = tid & 31;
        float p = dsh[l] * fc_w[c * Lc + l]
                + dsh[l + 32] * fc_w[c * Lc + l + 32];
        #pragma unroll
        for (int off = 16; off > 0; off >>= 1)
            p += __shfl_down_sync(0xffffffffu, p, off);
        if (l == 0) out[b * 2 + c] = p + fc_b[c];
    }
}

extern "C" void kernel_launch(void* const* d_in, const int* in_sizes, int n_in,
                              void* d_out, int out_size)
{
    (void)in_sizes; (void)n_in; (void)out_size;
    const float* ts   = (const float*)d_in[0];
    const float* shp  = (const float*)d_in[1];
    const float* fc_w = (const float*)d_in[2];
    const float* fc_b = (const float*)d_in[3];
    float* out        = (float*)d_out;
    shapelet_hmma<<<Bc, 128>>>(ts, shp, fc_w, fc_b, out);
}